// round 6
// baseline (speedup 1.0000x reference)
#include <cuda_runtime.h>
#include <cstdint>

// ---------------------------------------------------------------------------
// KWTA: per-sample k-th-largest threshold + masked NHWC->NCHW transpose.
// x: (32, 56, 56, 256) fp32.  dim = 802816, k = ceil(0.2*dim) = 160564.
// out[b][c][h][w] = masked x[b][h][w][c]
// ---------------------------------------------------------------------------

#define B          32
#define HW         3136            // 56*56
#define C          256
#define DIM        802816          // HW*C
#define DIM4       200704          // DIM/4
#define KSEL       160564u
#define NBINS      2048            // top-11-bit histogram
#define CAP        131072          // candidate buffer per sample
#define HBLOCKS    98              // 98*2048 float4 = DIM4 per sample

__device__ unsigned g_hist[B * NBINS];
__device__ unsigned g_cnt[B];
__device__ unsigned g_bin[B];
__device__ unsigned g_kprime[B];
__device__ unsigned g_cand[B * CAP];
__device__ float    g_thresh[B];

__device__ __forceinline__ unsigned f2key(float f) {
    unsigned u = __float_as_uint(f);
    return (u & 0x80000000u) ? ~u : (u | 0x80000000u);
}

// ---- 1. zero scratch -------------------------------------------------------
__global__ void zero_kernel() {
    int i = blockIdx.x * blockDim.x + threadIdx.x;
    if (i < B * NBINS) g_hist[i] = 0;
    if (i < B) g_cnt[i] = 0;
}

// ---- 2. coarse histogram: match_any-aggregated smem atomics ----------------
__global__ __launch_bounds__(256) void hist_kernel(const float4* __restrict__ x) {
    __shared__ unsigned sh[NBINS];
    int tid = threadIdx.x;
    int lane = tid & 31;
    #pragma unroll
    for (int i = tid; i < NBINS; i += 256) sh[i] = 0;
    __syncthreads();

    int s = blockIdx.y;
    const float4* p = x + (size_t)s * DIM4 + (size_t)blockIdx.x * 2048;
    #pragma unroll
    for (int it = 0; it < 8; it++) {
        float4 v = p[tid + it * 256];
        unsigned bins[4] = { f2key(v.x) >> 21, f2key(v.y) >> 21,
                             f2key(v.z) >> 21, f2key(v.w) >> 21 };
        #pragma unroll
        for (int q = 0; q < 4; q++) {
            unsigned m = __match_any_sync(0xffffffffu, bins[q]);
            if (lane == (__ffs(m) - 1))
                atomicAdd(&sh[bins[q]], (unsigned)__popc(m));
        }
    }
    __syncthreads();
    for (int i = tid; i < NBINS; i += 256) {
        unsigned c = sh[i];
        if (c) atomicAdd(&g_hist[s * NBINS + i], c);
    }
}

// ---- 3. find target bin + residual k' per sample ---------------------------
__global__ void scan_kernel() {
    __shared__ unsigned sh[NBINS];
    int s = blockIdx.x;
    int tid = threadIdx.x;
    for (int i = tid; i < NBINS; i += blockDim.x) sh[i] = g_hist[s * NBINS + i];
    __syncthreads();
    if (tid == 0) {
        unsigned cum = 0;
        int b = NBINS - 1;
        for (; b >= 0; b--) {
            cum += sh[b];
            if (cum >= KSEL) break;
        }
        if (b < 0) b = 0;
        g_bin[s] = (unsigned)b;
        g_kprime[s] = KSEL - (cum - sh[b]);
    }
}

// ---- 4. compact: ballot-aggregated staging, ONE global atomic/block --------
__global__ __launch_bounds__(256) void compact_kernel(const float4* __restrict__ x) {
    __shared__ unsigned stage[8192];
    __shared__ unsigned s_cnt;
    __shared__ unsigned s_base;

    int s = blockIdx.y;
    unsigned bin = g_bin[s];
    int tid = threadIdx.x;
    int lane = tid & 31;
    if (tid == 0) s_cnt = 0;
    __syncthreads();

    const float4* p = x + (size_t)s * DIM4 + (size_t)blockIdx.x * 2048;
    #pragma unroll
    for (int it = 0; it < 8; it++) {
        float4 v = p[tid + it * 256];
        unsigned keys[4] = { f2key(v.x), f2key(v.y), f2key(v.z), f2key(v.w) };
        #pragma unroll
        for (int q = 0; q < 4; q++) {
            bool m = (keys[q] >> 21) == bin;
            unsigned bal = __ballot_sync(0xffffffffu, m);
            if (bal) {
                int leader = __ffs(bal) - 1;
                unsigned base = 0;
                if (lane == leader) base = atomicAdd(&s_cnt, (unsigned)__popc(bal));
                base = __shfl_sync(0xffffffffu, base, leader);
                if (m) stage[base + (unsigned)__popc(bal & ((1u << lane) - 1u))] = keys[q];
            }
        }
    }
    __syncthreads();

    unsigned cnt = s_cnt;
    if (tid == 0 && cnt) s_base = atomicAdd(&g_cnt[s], cnt);
    __syncthreads();

    if (cnt) {
        unsigned base = s_base;
        for (unsigned i = tid; i < cnt; i += 256) {
            unsigned pos = base + i;
            if (pos < CAP) g_cand[(size_t)s * CAP + pos] = stage[i];
        }
    }
}

// ---- 5. exact radix select over candidates (3 x 7-bit passes) --------------
__global__ __launch_bounds__(256) void select_kernel() {
    __shared__ unsigned sh[128];
    __shared__ unsigned s_prefix, s_kp;
    int s = blockIdx.x;
    int tid = threadIdx.x;
    unsigned n = g_cnt[s];
    if (n > CAP) n = CAP;
    unsigned prefix = g_bin[s] << 21;
    unsigned kp = g_kprime[s];

    #pragma unroll
    for (int pass = 0; pass < 3; pass++) {
        int shift = 14 - pass * 7;
        unsigned pmask = 0xFFFFFFFFu << (shift + 7);
        for (int i = tid; i < 128; i += 256) sh[i] = 0;
        __syncthreads();
        for (unsigned i = tid; i < n; i += 256) {
            unsigned key = g_cand[(size_t)s * CAP + i];
            if ((key & pmask) == prefix)
                atomicAdd(&sh[(key >> shift) & 127u], 1u);
        }
        __syncthreads();
        if (tid == 0) {
            unsigned cum = 0;
            int d = 127;
            for (; d >= 0; d--) {
                cum += sh[d];
                if (cum >= kp) break;
            }
            if (d < 0) d = 0;
            s_kp = kp - (cum - sh[d]);
            s_prefix = prefix | ((unsigned)d << shift);
        }
        __syncthreads();
        prefix = s_prefix;
        kp = s_kp;
        __syncthreads();
    }

    if (tid == 0) {
        unsigned key = prefix;
        unsigned u = (key & 0x80000000u) ? (key & 0x7FFFFFFFu) : ~key;
        g_thresh[s] = __uint_as_float(u);
    }
}

// ---- 6. masked transpose: 64x64 tile, float4 global on BOTH sides ----------
__global__ __launch_bounds__(256) void mask_transpose_kernel(const float* __restrict__ x,
                                                             float* __restrict__ out) {
    __shared__ float tile[64 * 65];   // tile[c][hw] layout, stride 65
    int b = blockIdx.z;
    float th = g_thresh[b];
    int c0 = blockIdx.x * 64;
    int hw0 = blockIdx.y * 64;
    const float* xin = x + (size_t)b * DIM;
    float* o = out + (size_t)b * DIM;

    int tx = threadIdx.x & 15;        // float4 index
    int ty = threadIdx.x >> 4;        // 0..15
    int c4 = 4 * tx;

    // load: float4 along c, scatter to tile[c][hw]
    #pragma unroll
    for (int j = 0; j < 4; j++) {
        int row = ty + 16 * j;        // hw within tile
        float4 v = *(const float4*)&xin[(size_t)(hw0 + row) * C + (c0 + c4)];
        v.x = (v.x >= th) ? v.x : 0.0f;
        v.y = (v.y >= th) ? v.y : 0.0f;
        v.z = (v.z >= th) ? v.z : 0.0f;
        v.w = (v.w >= th) ? v.w : 0.0f;
        tile[(c4 + 0) * 65 + row] = v.x;
        tile[(c4 + 1) * 65 + row] = v.y;
        tile[(c4 + 2) * 65 + row] = v.z;
        tile[(c4 + 3) * 65 + row] = v.w;
    }
    __syncthreads();

    // store: gather 4 consecutive hw for one c, float4 along hw
    #pragma unroll
    for (int j = 0; j < 4; j++) {
        int crow = ty + 16 * j;
        float4 w;
        w.x = tile[crow * 65 + 4 * tx + 0];
        w.y = tile[crow * 65 + 4 * tx + 1];
        w.z = tile[crow * 65 + 4 * tx + 2];
        w.w = tile[crow * 65 + 4 * tx + 3];
        *(float4*)&o[(size_t)(c0 + crow) * HW + (hw0 + 4 * tx)] = w;
    }
}

// ---------------------------------------------------------------------------
extern "C" void kernel_launch(void* const* d_in, const int* in_sizes, int n_in,
                              void* d_out, int out_size) {
    (void)in_sizes; (void)n_in; (void)out_size;
    const float* x = (const float*)d_in[0];
    float* out = (float*)d_out;

    zero_kernel<<<(B * NBINS + 255) / 256, 256>>>();

    dim3 hgrid(HBLOCKS, B);
    hist_kernel<<<hgrid, 256>>>((const float4*)x);

    scan_kernel<<<B, 256>>>();

    compact_kernel<<<hgrid, 256>>>((const float4*)x);

    select_kernel<<<B, 256>>>();

    dim3 tgrid(C / 64, HW / 64, B);
    mask_transpose_kernel<<<tgrid, 256>>>(x, out);
}

// round 7
// speedup vs baseline: 1.8093x; 1.8093x over previous
#include <cuda_runtime.h>
#include <cstdint>

// ---------------------------------------------------------------------------
// KWTA: per-sample k-th-largest threshold + masked NHWC->NCHW transpose.
// x: (32, 56, 56, 256) fp32.  dim = 802816, k = ceil(0.2*dim) = 160564.
// out[b][c][h][w] = masked x[b][h][w][c]
// ---------------------------------------------------------------------------

#define B          32
#define HW         3136            // 56*56
#define C          256
#define DIM        802816          // HW*C
#define DIM4       200704          // DIM/4
#define KSEL       160564u
#define NBINS      2048            // top-11-bit histogram
#define CAP        131072          // candidate buffer per sample
#define HBLOCKS    98              // 98*2048 float4 = DIM4 per sample

__device__ unsigned g_hist[B * NBINS];
__device__ unsigned g_cnt[B];
__device__ unsigned g_bin[B];
__device__ unsigned g_kprime[B];
__device__ unsigned g_cand[B * CAP];
__device__ float    g_thresh[B];

__device__ __forceinline__ unsigned f2key(float f) {
    unsigned u = __float_as_uint(f);
    return (u & 0x80000000u) ? ~u : (u | 0x80000000u);
}

// ---- 1. zero scratch -------------------------------------------------------
__global__ void zero_kernel() {
    int i = blockIdx.x * blockDim.x + threadIdx.x;
    if (i < B * NBINS) g_hist[i] = 0;
    if (i < B) g_cnt[i] = 0;
}

// ---- 2. coarse histogram: two smem replicas (by warp parity) ---------------
__global__ __launch_bounds__(256) void hist_kernel(const float4* __restrict__ x) {
    __shared__ unsigned sh[2 * NBINS];
    int tid = threadIdx.x;
    unsigned rep = ((tid >> 5) & 1) * NBINS;   // warp-parity replica
    #pragma unroll
    for (int i = tid; i < 2 * NBINS; i += 256) sh[i] = 0;
    __syncthreads();

    int s = blockIdx.y;
    const float4* p = x + (size_t)s * DIM4 + (size_t)blockIdx.x * 2048;
    #pragma unroll
    for (int it = 0; it < 8; it++) {
        float4 v = p[tid + it * 256];
        atomicAdd(&sh[rep + (f2key(v.x) >> 21)], 1u);
        atomicAdd(&sh[rep + (f2key(v.y) >> 21)], 1u);
        atomicAdd(&sh[rep + (f2key(v.z) >> 21)], 1u);
        atomicAdd(&sh[rep + (f2key(v.w) >> 21)], 1u);
    }
    __syncthreads();
    for (int i = tid; i < NBINS; i += 256) {
        unsigned c = sh[i] + sh[NBINS + i];
        if (c) atomicAdd(&g_hist[s * NBINS + i], c);
    }
}

// ---- 3. find target bin + residual k' per sample ---------------------------
__global__ void scan_kernel() {
    __shared__ unsigned sh[NBINS];
    int s = blockIdx.x;
    int tid = threadIdx.x;
    for (int i = tid; i < NBINS; i += blockDim.x) sh[i] = g_hist[s * NBINS + i];
    __syncthreads();
    if (tid == 0) {
        unsigned cum = 0;
        int b = NBINS - 1;
        for (; b >= 0; b--) {
            cum += sh[b];
            if (cum >= KSEL) break;
        }
        if (b < 0) b = 0;
        g_bin[s] = (unsigned)b;
        g_kprime[s] = KSEL - (cum - sh[b]);
    }
}

// ---- 4. compact: per-element smem atomic staging, ONE global atomic/block --
__global__ __launch_bounds__(256) void compact_kernel(const float4* __restrict__ x) {
    __shared__ unsigned stage[8192];
    __shared__ unsigned s_cnt;
    __shared__ unsigned s_base;

    int s = blockIdx.y;
    unsigned bin = g_bin[s];
    int tid = threadIdx.x;
    if (tid == 0) s_cnt = 0;
    __syncthreads();

    const float4* p = x + (size_t)s * DIM4 + (size_t)blockIdx.x * 2048;
    #pragma unroll
    for (int it = 0; it < 8; it++) {
        float4 v = p[tid + it * 256];
        unsigned keys[4] = { f2key(v.x), f2key(v.y), f2key(v.z), f2key(v.w) };
        #pragma unroll
        for (int q = 0; q < 4; q++) {
            if ((keys[q] >> 21) == bin) {
                unsigned pos = atomicAdd(&s_cnt, 1u);   // rare (~3% of elements)
                stage[pos] = keys[q];
            }
        }
    }
    __syncthreads();

    unsigned cnt = s_cnt;
    if (tid == 0 && cnt) s_base = atomicAdd(&g_cnt[s], cnt);
    __syncthreads();

    if (cnt) {
        unsigned base = s_base;
        for (unsigned i = tid; i < cnt; i += 256) {
            unsigned pos = base + i;
            if (pos < CAP) g_cand[(size_t)s * CAP + pos] = stage[i];
        }
    }
}

// ---- 5. exact radix select over candidates (3 x 7-bit passes) --------------
__global__ __launch_bounds__(256) void select_kernel() {
    __shared__ unsigned sh[128];
    __shared__ unsigned s_prefix, s_kp;
    int s = blockIdx.x;
    int tid = threadIdx.x;
    unsigned n = g_cnt[s];
    if (n > CAP) n = CAP;
    unsigned prefix = g_bin[s] << 21;
    unsigned kp = g_kprime[s];

    #pragma unroll
    for (int pass = 0; pass < 3; pass++) {
        int shift = 14 - pass * 7;
        unsigned pmask = 0xFFFFFFFFu << (shift + 7);
        for (int i = tid; i < 128; i += 256) sh[i] = 0;
        __syncthreads();
        for (unsigned i = tid; i < n; i += 256) {
            unsigned key = g_cand[(size_t)s * CAP + i];
            if ((key & pmask) == prefix)
                atomicAdd(&sh[(key >> shift) & 127u], 1u);
        }
        __syncthreads();
        if (tid == 0) {
            unsigned cum = 0;
            int d = 127;
            for (; d >= 0; d--) {
                cum += sh[d];
                if (cum >= kp) break;
            }
            if (d < 0) d = 0;
            s_kp = kp - (cum - sh[d]);
            s_prefix = prefix | ((unsigned)d << shift);
        }
        __syncthreads();
        prefix = s_prefix;
        kp = s_kp;
        __syncthreads();
    }

    if (tid == 0) {
        unsigned key = prefix;
        unsigned u = (key & 0x80000000u) ? (key & 0x7FFFFFFFu) : ~key;
        g_thresh[s] = __uint_as_float(u);
    }
}

// ---- 6. masked transpose: (hw, c) -> (c, hw), 32x32 tile (R3-proven) -------
__global__ __launch_bounds__(256) void mask_transpose_kernel(const float* __restrict__ x,
                                                             float* __restrict__ out) {
    __shared__ float tile[32][33];
    int b = blockIdx.z;
    float th = g_thresh[b];
    int c0 = blockIdx.x * 32;
    int hw0 = blockIdx.y * 32;
    const float* xin = x + (size_t)b * DIM;
    float* o = out + (size_t)b * DIM;
    int tx = threadIdx.x, ty = threadIdx.y;

    #pragma unroll
    for (int j = 0; j < 32; j += 8) {
        float v = xin[(size_t)(hw0 + ty + j) * C + (c0 + tx)];
        tile[ty + j][tx] = (v >= th) ? v : 0.0f;
    }
    __syncthreads();
    #pragma unroll
    for (int j = 0; j < 32; j += 8) {
        o[(size_t)(c0 + ty + j) * HW + (hw0 + tx)] = tile[tx][ty + j];
    }
}

// ---------------------------------------------------------------------------
extern "C" void kernel_launch(void* const* d_in, const int* in_sizes, int n_in,
                              void* d_out, int out_size) {
    (void)in_sizes; (void)n_in; (void)out_size;
    const float* x = (const float*)d_in[0];
    float* out = (float*)d_out;

    zero_kernel<<<(B * NBINS + 255) / 256, 256>>>();

    dim3 hgrid(HBLOCKS, B);
    hist_kernel<<<hgrid, 256>>>((const float4*)x);

    scan_kernel<<<B, 256>>>();

    compact_kernel<<<hgrid, 256>>>((const float4*)x);

    select_kernel<<<B, 256>>>();

    dim3 tblk(32, 8);
    dim3 tgrid(C / 32, HW / 32, B);
    mask_transpose_kernel<<<tgrid, tblk>>>(x, out);
}

// round 8
// speedup vs baseline: 1.8896x; 1.0444x over previous
#include <cuda_runtime.h>
#include <cstdint>

// ---------------------------------------------------------------------------
// KWTA: per-sample k-th-largest threshold + masked NHWC->NCHW transpose.
// x: (32, 56, 56, 256) fp32.  dim = 802816, k = ceil(0.2*dim) = 160564.
// out[b][c][h][w] = masked x[b][h][w][c]
// ---------------------------------------------------------------------------

#define B          32
#define HW         3136            // 56*56
#define C          256
#define DIM        802816          // HW*C
#define DIM4       200704          // DIM/4
#define KSEL       160564u
#define NBINS      2048            // top-11-bit histogram
#define CAP        131072          // candidate buffer per sample
#define HBLOCKS    98              // 98*2048 float4 = DIM4 per sample
#define STAGE      2048            // smem staging entries (expected ~287 matches/blk)

__device__ unsigned g_hist[B * NBINS];
__device__ unsigned g_cnt[B];
__device__ unsigned g_bin[B];
__device__ unsigned g_kprime[B];
__device__ unsigned g_cand[B * CAP];
__device__ float    g_thresh[B];

__device__ __forceinline__ unsigned f2key(float f) {
    unsigned u = __float_as_uint(f);
    return (u & 0x80000000u) ? ~u : (u | 0x80000000u);
}

// ---- 1. zero scratch -------------------------------------------------------
__global__ void zero_kernel() {
    int i = blockIdx.x * blockDim.x + threadIdx.x;
    if (i < B * NBINS) g_hist[i] = 0;
    if (i < B) g_cnt[i] = 0;
}

// ---- 2. coarse histogram: two smem replicas (by warp parity) ---------------
__global__ __launch_bounds__(256) void hist_kernel(const float4* __restrict__ x) {
    __shared__ unsigned sh[2 * NBINS];
    int tid = threadIdx.x;
    unsigned rep = ((tid >> 5) & 1) * NBINS;
    #pragma unroll
    for (int i = tid; i < 2 * NBINS; i += 256) sh[i] = 0;
    __syncthreads();

    int s = blockIdx.y;
    const float4* p = x + (size_t)s * DIM4 + (size_t)blockIdx.x * 2048;
    #pragma unroll
    for (int it = 0; it < 8; it++) {
        float4 v = p[tid + it * 256];
        atomicAdd(&sh[rep + (f2key(v.x) >> 21)], 1u);
        atomicAdd(&sh[rep + (f2key(v.y) >> 21)], 1u);
        atomicAdd(&sh[rep + (f2key(v.z) >> 21)], 1u);
        atomicAdd(&sh[rep + (f2key(v.w) >> 21)], 1u);
    }
    __syncthreads();
    for (int i = tid; i < NBINS; i += 256) {
        unsigned c = sh[i] + sh[NBINS + i];
        if (c) atomicAdd(&g_hist[s * NBINS + i], c);
    }
}

// ---- 3. find target bin + residual k' per sample ---------------------------
__global__ void scan_kernel() {
    __shared__ unsigned sh[NBINS];
    int s = blockIdx.x;
    int tid = threadIdx.x;
    for (int i = tid; i < NBINS; i += blockDim.x) sh[i] = g_hist[s * NBINS + i];
    __syncthreads();
    if (tid == 0) {
        unsigned cum = 0;
        int b = NBINS - 1;
        for (; b >= 0; b--) {
            cum += sh[b];
            if (cum >= KSEL) break;
        }
        if (b < 0) b = 0;
        g_bin[s] = (unsigned)b;
        g_kprime[s] = KSEL - (cum - sh[b]);
    }
}

// ---- 4. compact: front-batched loads, small smem stage + overflow path -----
__global__ __launch_bounds__(256) void compact_kernel(const float4* __restrict__ x) {
    __shared__ unsigned stage[STAGE];
    __shared__ unsigned s_cnt;
    __shared__ unsigned s_base;

    int s = blockIdx.y;
    unsigned bin = g_bin[s];
    int tid = threadIdx.x;
    if (tid == 0) s_cnt = 0;
    __syncthreads();

    const float4* p = x + (size_t)s * DIM4 + (size_t)blockIdx.x * 2048;

    // front-batch all 8 float4 loads (MLP=8 per thread)
    float4 v[8];
    #pragma unroll
    for (int it = 0; it < 8; it++) v[it] = p[tid + it * 256];

    #pragma unroll
    for (int it = 0; it < 8; it++) {
        unsigned keys[4] = { f2key(v[it].x), f2key(v[it].y),
                             f2key(v[it].z), f2key(v[it].w) };
        #pragma unroll
        for (int q = 0; q < 4; q++) {
            if ((keys[q] >> 21) == bin) {
                unsigned pos = atomicAdd(&s_cnt, 1u);   // rare (~3.5%)
                if (pos < STAGE) {
                    stage[pos] = keys[q];
                } else {                                 // overflow: direct global
                    unsigned g = atomicAdd(&g_cnt[s], 1u);
                    if (g < CAP) g_cand[(size_t)s * CAP + g] = keys[q];
                }
            }
        }
    }
    __syncthreads();

    unsigned cnt = s_cnt;
    if (cnt > STAGE) cnt = STAGE;
    if (tid == 0 && cnt) s_base = atomicAdd(&g_cnt[s], cnt);
    __syncthreads();

    if (cnt) {
        unsigned base = s_base;
        for (unsigned i = tid; i < cnt; i += 256) {
            unsigned pos = base + i;
            if (pos < CAP) g_cand[(size_t)s * CAP + pos] = stage[i];
        }
    }
}

// ---- 5. exact radix select over candidates (3 x 7-bit passes) --------------
__global__ __launch_bounds__(256) void select_kernel() {
    __shared__ unsigned sh[128];
    __shared__ unsigned s_prefix, s_kp;
    int s = blockIdx.x;
    int tid = threadIdx.x;
    unsigned n = g_cnt[s];
    if (n > CAP) n = CAP;
    unsigned prefix = g_bin[s] << 21;
    unsigned kp = g_kprime[s];

    #pragma unroll
    for (int pass = 0; pass < 3; pass++) {
        int shift = 14 - pass * 7;
        unsigned pmask = 0xFFFFFFFFu << (shift + 7);
        for (int i = tid; i < 128; i += 256) sh[i] = 0;
        __syncthreads();
        for (unsigned i = tid; i < n; i += 256) {
            unsigned key = g_cand[(size_t)s * CAP + i];
            if ((key & pmask) == prefix)
                atomicAdd(&sh[(key >> shift) & 127u], 1u);
        }
        __syncthreads();
        if (tid == 0) {
            unsigned cum = 0;
            int d = 127;
            for (; d >= 0; d--) {
                cum += sh[d];
                if (cum >= kp) break;
            }
            if (d < 0) d = 0;
            s_kp = kp - (cum - sh[d]);
            s_prefix = prefix | ((unsigned)d << shift);
        }
        __syncthreads();
        prefix = s_prefix;
        kp = s_kp;
        __syncthreads();
    }

    if (tid == 0) {
        unsigned key = prefix;
        unsigned u = (key & 0x80000000u) ? (key & 0x7FFFFFFFu) : ~key;
        g_thresh[s] = __uint_as_float(u);
    }
}

// ---- 6. masked transpose: 64x64 tile, float4 global on BOTH sides ----------
__global__ __launch_bounds__(256) void mask_transpose_kernel(const float* __restrict__ x,
                                                             float* __restrict__ out) {
    __shared__ float tile[64 * 65];   // tile[c][hw], stride 65
    int b = blockIdx.z;
    float th = g_thresh[b];
    int c0 = blockIdx.x * 64;
    int hw0 = blockIdx.y * 64;
    const float* xin = x + (size_t)b * DIM;
    float* o = out + (size_t)b * DIM;

    int tx = threadIdx.x & 15;        // float4 index
    int ty = threadIdx.x >> 4;        // 0..15
    int c4 = 4 * tx;

    // load: float4 along c, scatter to tile[c][hw]
    #pragma unroll
    for (int j = 0; j < 4; j++) {
        int row = ty + 16 * j;        // hw within tile
        float4 v = *(const float4*)&xin[(size_t)(hw0 + row) * C + (c0 + c4)];
        v.x = (v.x >= th) ? v.x : 0.0f;
        v.y = (v.y >= th) ? v.y : 0.0f;
        v.z = (v.z >= th) ? v.z : 0.0f;
        v.w = (v.w >= th) ? v.w : 0.0f;
        tile[(c4 + 0) * 65 + row] = v.x;
        tile[(c4 + 1) * 65 + row] = v.y;
        tile[(c4 + 2) * 65 + row] = v.z;
        tile[(c4 + 3) * 65 + row] = v.w;
    }
    __syncthreads();

    // store: gather 4 consecutive hw for one c, float4 along hw
    #pragma unroll
    for (int j = 0; j < 4; j++) {
        int crow = ty + 16 * j;
        float4 w;
        w.x = tile[crow * 65 + 4 * tx + 0];
        w.y = tile[crow * 65 + 4 * tx + 1];
        w.z = tile[crow * 65 + 4 * tx + 2];
        w.w = tile[crow * 65 + 4 * tx + 3];
        *(float4*)&o[(size_t)(c0 + crow) * HW + (hw0 + 4 * tx)] = w;
    }
}

// ---------------------------------------------------------------------------
extern "C" void kernel_launch(void* const* d_in, const int* in_sizes, int n_in,
                              void* d_out, int out_size) {
    (void)in_sizes; (void)n_in; (void)out_size;
    const float* x = (const float*)d_in[0];
    float* out = (float*)d_out;

    zero_kernel<<<(B * NBINS + 255) / 256, 256>>>();

    dim3 hgrid(HBLOCKS, B);
    hist_kernel<<<hgrid, 256>>>((const float4*)x);

    scan_kernel<<<B, 256>>>();

    compact_kernel<<<hgrid, 256>>>((const float4*)x);

    select_kernel<<<B, 256>>>();

    dim3 tgrid(C / 64, HW / 64, B);
    mask_transpose_kernel<<<tgrid, 256>>>(x, out);
}

// round 10
// speedup vs baseline: 1.8962x; 1.0035x over previous
#include <cuda_runtime.h>
#include <cstdint>

// ---------------------------------------------------------------------------
// KWTA: per-sample k-th-largest threshold + masked NHWC->NCHW transpose.
// x: (32, 56, 56, 256) fp32.  dim = 802816, k = ceil(0.2*dim) = 160564.
// out[b][c][h][w] = masked x[b][h][w][c]
// ---------------------------------------------------------------------------

#define B          32
#define HW         3136            // 56*56
#define C          256
#define DIM        802816          // HW*C
#define DIM4       200704          // DIM/4
#define KSEL       160564u
#define NBINS      2048            // top-11-bit histogram
#define CAP        131072          // candidate buffer per sample
#define HBLOCKS    98              // 98*2048 float4 = DIM4 per sample
#define STAGE      2048            // smem staging entries (expected ~287 matches/blk)

__device__ unsigned g_hist[B * NBINS];   // zero at start; re-zeroed by scan_kernel
__device__ unsigned g_cnt[B];            // zero at start; re-zeroed by select_kernel
__device__ unsigned g_bin[B];
__device__ unsigned g_kprime[B];
__device__ unsigned g_cand[B * CAP];
__device__ float    g_thresh[B];

__device__ __forceinline__ unsigned f2key(float f) {
    unsigned u = __float_as_uint(f);
    return (u & 0x80000000u) ? ~u : (u | 0x80000000u);
}

// ---- 1. coarse histogram: two smem replicas (by warp parity) ---------------
__global__ __launch_bounds__(256) void hist_kernel(const float4* __restrict__ x) {
    __shared__ unsigned sh[2 * NBINS];
    int tid = threadIdx.x;
    unsigned rep = ((tid >> 5) & 1) * NBINS;
    #pragma unroll
    for (int i = tid; i < 2 * NBINS; i += 256) sh[i] = 0;
    __syncthreads();

    int s = blockIdx.y;
    const float4* p = x + (size_t)s * DIM4 + (size_t)blockIdx.x * 2048;
    #pragma unroll
    for (int it = 0; it < 8; it++) {
        float4 v = p[tid + it * 256];
        atomicAdd(&sh[rep + (f2key(v.x) >> 21)], 1u);
        atomicAdd(&sh[rep + (f2key(v.y) >> 21)], 1u);
        atomicAdd(&sh[rep + (f2key(v.z) >> 21)], 1u);
        atomicAdd(&sh[rep + (f2key(v.w) >> 21)], 1u);
    }
    __syncthreads();
    for (int i = tid; i < NBINS; i += 256) {
        unsigned c = sh[i] + sh[NBINS + i];
        if (c) atomicAdd(&g_hist[s * NBINS + i], c);
    }
}

// ---- 2. find target bin + k'; then re-zero g_hist for next replay ----------
__global__ void scan_kernel() {
    __shared__ unsigned sh[NBINS];
    int s = blockIdx.x;
    int tid = threadIdx.x;
    for (int i = tid; i < NBINS; i += blockDim.x) sh[i] = g_hist[s * NBINS + i];
    __syncthreads();
    if (tid == 0) {
        unsigned cum = 0;
        int b = NBINS - 1;
        for (; b >= 0; b--) {
            cum += sh[b];
            if (cum >= KSEL) break;
        }
        if (b < 0) b = 0;
        g_bin[s] = (unsigned)b;
        g_kprime[s] = KSEL - (cum - sh[b]);
    }
    // restore the all-zero invariant (replaces zero_kernel)
    for (int i = tid; i < NBINS; i += blockDim.x) g_hist[s * NBINS + i] = 0;
}

// ---- 3. compact: front-batched loads, small smem stage + overflow path -----
__global__ __launch_bounds__(256) void compact_kernel(const float4* __restrict__ x) {
    __shared__ unsigned stage[STAGE];
    __shared__ unsigned s_cnt;
    __shared__ unsigned s_base;

    int s = blockIdx.y;
    unsigned bin = g_bin[s];
    int tid = threadIdx.x;
    if (tid == 0) s_cnt = 0;
    __syncthreads();

    const float4* p = x + (size_t)s * DIM4 + (size_t)blockIdx.x * 2048;

    float4 v[8];
    #pragma unroll
    for (int it = 0; it < 8; it++) v[it] = p[tid + it * 256];

    #pragma unroll
    for (int it = 0; it < 8; it++) {
        unsigned keys[4] = { f2key(v[it].x), f2key(v[it].y),
                             f2key(v[it].z), f2key(v[it].w) };
        #pragma unroll
        for (int q = 0; q < 4; q++) {
            if ((keys[q] >> 21) == bin) {
                unsigned pos = atomicAdd(&s_cnt, 1u);   // rare (~3.5%)
                if (pos < STAGE) {
                    stage[pos] = keys[q];
                } else {
                    unsigned g = atomicAdd(&g_cnt[s], 1u);
                    if (g < CAP) g_cand[(size_t)s * CAP + g] = keys[q];
                }
            }
        }
    }
    __syncthreads();

    unsigned cnt = s_cnt;
    if (cnt > STAGE) cnt = STAGE;
    if (tid == 0 && cnt) s_base = atomicAdd(&g_cnt[s], cnt);
    __syncthreads();

    if (cnt) {
        unsigned base = s_base;
        for (unsigned i = tid; i < cnt; i += 256) {
            unsigned pos = base + i;
            if (pos < CAP) g_cand[(size_t)s * CAP + pos] = stage[i];
        }
    }
}

// ---- 4. exact radix select; then re-zero g_cnt ------------------------------
__global__ __launch_bounds__(256) void select_kernel() {
    __shared__ unsigned sh[128];
    __shared__ unsigned s_prefix, s_kp;
    int s = blockIdx.x;
    int tid = threadIdx.x;
    unsigned n = g_cnt[s];
    if (n > CAP) n = CAP;
    unsigned prefix = g_bin[s] << 21;
    unsigned kp = g_kprime[s];

    #pragma unroll
    for (int pass = 0; pass < 3; pass++) {
        int shift = 14 - pass * 7;
        unsigned pmask = 0xFFFFFFFFu << (shift + 7);
        for (int i = tid; i < 128; i += 256) sh[i] = 0;
        __syncthreads();
        for (unsigned i = tid; i < n; i += 256) {
            unsigned key = g_cand[(size_t)s * CAP + i];
            if ((key & pmask) == prefix)
                atomicAdd(&sh[(key >> shift) & 127u], 1u);
        }
        __syncthreads();
        if (tid == 0) {
            unsigned cum = 0;
            int d = 127;
            for (; d >= 0; d--) {
                cum += sh[d];
                if (cum >= kp) break;
            }
            if (d < 0) d = 0;
            s_kp = kp - (cum - sh[d]);
            s_prefix = prefix | ((unsigned)d << shift);
        }
        __syncthreads();
        prefix = s_prefix;
        kp = s_kp;
        __syncthreads();
    }

    if (tid == 0) {
        unsigned key = prefix;
        unsigned u = (key & 0x80000000u) ? (key & 0x7FFFFFFFu) : ~key;
        g_thresh[s] = __uint_as_float(u);
        g_cnt[s] = 0;   // restore invariant (replaces zero_kernel)
    }
}

// ---- 5. masked transpose: 64x64 tile, float4 both sides, STREAMING stores --
__global__ __launch_bounds__(256) void mask_transpose_kernel(const float* __restrict__ x,
                                                             float* __restrict__ out) {
    __shared__ float tile[64 * 65];   // tile[c][hw], stride 65
    int b = blockIdx.z;
    float th = g_thresh[b];
    int c0 = blockIdx.x * 64;
    int hw0 = blockIdx.y * 64;
    const float* xin = x + (size_t)b * DIM;
    float* o = out + (size_t)b * DIM;

    int tx = threadIdx.x & 15;        // float4 index
    int ty = threadIdx.x >> 4;        // 0..15
    int c4 = 4 * tx;

    #pragma unroll
    for (int j = 0; j < 4; j++) {
        int row = ty + 16 * j;        // hw within tile
        float4 v = *(const float4*)&xin[(size_t)(hw0 + row) * C + (c0 + c4)];
        v.x = (v.x >= th) ? v.x : 0.0f;
        v.y = (v.y >= th) ? v.y : 0.0f;
        v.z = (v.z >= th) ? v.z : 0.0f;
        v.w = (v.w >= th) ? v.w : 0.0f;
        tile[(c4 + 0) * 65 + row] = v.x;
        tile[(c4 + 1) * 65 + row] = v.y;
        tile[(c4 + 2) * 65 + row] = v.z;
        tile[(c4 + 3) * 65 + row] = v.w;
    }
    __syncthreads();

    #pragma unroll
    for (int j = 0; j < 4; j++) {
        int crow = ty + 16 * j;
        float4 w;
        w.x = tile[crow * 65 + 4 * tx + 0];
        w.y = tile[crow * 65 + 4 * tx + 1];
        w.z = tile[crow * 65 + 4 * tx + 2];
        w.w = tile[crow * 65 + 4 * tx + 3];
        // streaming store: out is never re-read; don't evict x from L2
        __stcs((float4*)&o[(size_t)(c0 + crow) * HW + (hw0 + 4 * tx)], w);
    }
}

// ---------------------------------------------------------------------------
extern "C" void kernel_launch(void* const* d_in, const int* in_sizes, int n_in,
                              void* d_out, int out_size) {
    (void)in_sizes; (void)n_in; (void)out_size;
    const float* x = (const float*)d_in[0];
    float* out = (float*)d_out;

    dim3 hgrid(HBLOCKS, B);
    hist_kernel<<<hgrid, 256>>>((const float4*)x);

    scan_kernel<<<B, 256>>>();

    compact_kernel<<<hgrid, 256>>>((const float4*)x);

    select_kernel<<<B, 256>>>();

    dim3 tgrid(C / 64, HW / 64, B);
    mask_transpose_kernel<<<tgrid, 256>>>(x, out);
}